// round 16
// baseline (speedup 1.0000x reference)
#include <cuda_runtime.h>
#include <cuda_fp16.h>
#include <math.h>
#include <stdint.h>

// Problem constants
#define D     1024
#define H_    16
#define HD    64
#define FF    4096
#define NB    2
#define LQ    2048
#define MROWS (NB * LQ)   // 4096
#define EPS   1e-5f

// ---------------------------------------------------------------------------
// Scratch (device globals — no allocation allowed)
// ---------------------------------------------------------------------------
__device__ __half g_x16   [MROWS * D];    // h id 0  (x16 -> hpre16 in place)
__device__ __half g_attn16[MROWS * D];    // h id 1  (attn16 -> sum16 reuse)
__device__ __half g_h16   [MROWS * D];    // h id 2
__device__ __half g_ff116 [MROWS * FF];   // h id 3
__device__ __half g_wqkvT16[3 * D * D];   // h id 4
__device__ __half g_woT16 [D * D];        // h id 5
__device__ __half g_w1T16 [FF * D];       // h id 6
__device__ __half g_w2T16 [D * FF];       // h id 7
__device__ __half g_qkv16 [MROWS * 3 * D];// h id 8

__device__ __forceinline__ __half* scratch_h(int id) {
    switch (id) {
        case 0:  return g_x16;
        case 1:  return g_attn16;
        case 2:  return g_h16;
        case 3:  return g_ff116;
        case 4:  return g_wqkvT16;
        case 5:  return g_woT16;
        case 6:  return g_w1T16;
        case 7:  return g_w2T16;
        default: return g_qkv16;
    }
}

// ---------------------------------------------------------------------------
// mma / async helpers (base sm_103 target OK)
// ---------------------------------------------------------------------------
__device__ __forceinline__ void mma_f16(float* c, const uint32_t* a, const uint32_t* b) {
    asm volatile(
        "mma.sync.aligned.m16n8k16.row.col.f32.f16.f16.f32 "
        "{%0,%1,%2,%3}, {%4,%5,%6,%7}, {%8,%9}, {%0,%1,%2,%3};"
        : "+f"(c[0]), "+f"(c[1]), "+f"(c[2]), "+f"(c[3])
        : "r"(a[0]), "r"(a[1]), "r"(a[2]), "r"(a[3]),
          "r"(b[0]), "r"(b[1]));
}

__device__ __forceinline__ uint32_t packh2(float a, float b) {
    __half2 h = __floats2half2_rn(a, b);
    return *(uint32_t*)&h;
}

__device__ __forceinline__ void cp_async16(uint32_t dst, const void* src) {
    asm volatile("cp.async.cg.shared.global [%0], [%1], 16;" :: "r"(dst), "l"(src));
}
__device__ __forceinline__ void cp_commit() {
    asm volatile("cp.async.commit_group;" ::: "memory");
}
__device__ __forceinline__ void cp_wait2() {
    asm volatile("cp.async.wait_group 2;" ::: "memory");
}

#define LDSM4(r0, r1, r2, r3, addr) \
    asm volatile("ldmatrix.sync.aligned.m8n8.x4.shared.b16 {%0,%1,%2,%3}, [%4];" \
                 : "=r"(r0), "=r"(r1), "=r"(r2), "=r"(r3) : "r"(addr))

#define LDSM4T(r0, r1, r2, r3, addr) \
    asm volatile("ldmatrix.sync.aligned.m8n8.x4.trans.shared.b16 {%0,%1,%2,%3}, [%4];" \
                 : "=r"(r0), "=r"(r1), "=r"(r2), "=r"(r3) : "r"(addr))

// 64B-row XOR swizzle (GEMM stages)
__device__ __forceinline__ int phys16(int row, int c) {
    return (row >> 1) * 8 + ((((row & 1) << 2) | c) ^ ((row >> 1) & 3));
}
// 128B-row XOR swizzle (attention tiles)
#define ATT_SEG(row, c) (((row) * 8) + ((c) ^ ((row) & 7)))

// ---------------------------------------------------------------------------
// Fused operand prep (R14-validated)
// ---------------------------------------------------------------------------
__device__ __forceinline__ void transpose_tile(const float* __restrict__ src,
                                               __half* __restrict__ dst,
                                               int R, int C, int bx, int by,
                                               float (*t)[33])
{
    const int tx = threadIdx.x & 31;
    const int ty = threadIdx.x >> 5;
    #pragma unroll
    for (int i = 0; i < 32; i += 8)
        t[ty + i][tx] = src[(size_t)(by + ty + i) * C + bx + tx];
    __syncthreads();
    #pragma unroll
    for (int i = 0; i < 32; i += 8)
        dst[(size_t)(bx + ty + i) * R + by + tx] = __float2half(t[tx][ty + i]);
}

__global__ __launch_bounds__(256)
void prep_k(const float* __restrict__ x,
            const float* __restrict__ w_qkv,
            const float* __restrict__ w_o,
            const float* __restrict__ w1,
            const float* __restrict__ w2)
{
    __shared__ float t[32][33];
    const int id = blockIdx.x;

    if (id < 4096) {
        uint32_t* d = (uint32_t*)g_x16;
        const int i = id * 256 + threadIdx.x;
        const float4 v = ((const float4*)x)[i];
        d[i * 2 + 0] = packh2(v.x, v.y);
        d[i * 2 + 1] = packh2(v.z, v.w);
    } else if (id < 7168) {
        const int b = id - 4096;
        transpose_tile(w_qkv, g_wqkvT16, D, 3 * D, (b % 96) * 32, (b / 96) * 32, t);
    } else if (id < 8192) {
        const int b = id - 7168;
        transpose_tile(w_o, g_woT16, D, D, (b % 32) * 32, (b / 32) * 32, t);
    } else if (id < 12288) {
        const int b = id - 8192;
        transpose_tile(w1, g_w1T16, D, FF, (b % 128) * 32, (b / 128) * 32, t);
    } else {
        const int b = id - 12288;
        transpose_tile(w2, g_w2T16, FF, D, (b % 32) * 32, (b / 32) * 32, t);
    }
}

// ---------------------------------------------------------------------------
// FP16 GEMM 128x128 (mainloop FROZEN). Epilogue: + bias, opt ReLU,
// opt fp16 residual add (resHid), fp16 output.
// ---------------------------------------------------------------------------
#define STAGE_B 16384
#define GEMM_SMEM (4 * STAGE_B)   // 65536

__global__ __launch_bounds__(256)
void gemm_f16(int Aid, int Bid, const float* __restrict__ bias,
              int Cid, int resHid, int M, int N, int K, int relu)
{
    extern __shared__ char smem[];
    const uint32_t smem_u = (uint32_t)__cvta_generic_to_shared(smem);

    const __half* A  = scratch_h(Aid);
    const __half* Bt = scratch_h(Bid);

    const int tid  = threadIdx.x;
    const int wid  = tid >> 5;
    const int lane = tid & 31;
    const int gid  = lane >> 2;
    const int tig  = lane & 3;
    const int warpM = (wid & 1) * 64;
    const int warpN = (wid >> 1) * 32;
    const int m0 = blockIdx.y * 128;
    const int n0 = blockIdx.x * 128;

    uint32_t ld_dst[4];
    const __half* ld_src[4];
    #pragma unroll
    for (int j = 0; j < 4; j++) {
        const int s   = j * 256 + tid;
        const int isB = s >= 512;
        const int ss  = s & 511;
        const int row = ss >> 2;
        const int c   = ss & 3;
        ld_dst[j] = (isB ? 8192u : 0u) + (uint32_t)phys16(row, c) * 16u;
        ld_src[j] = (isB ? Bt + (size_t)(n0 + row) * K
                         : A  + (size_t)(m0 + row) * K) + c * 8;
    }

    const int hi = lane >> 4;
    const int rr = (lane & 7) + ((lane >> 3) & 1) * 8;
    uint32_t a_off[2][4], b_off[2][2];
    {
        const int ra = warpM + rr;
        const int la = ra >> 1, xa = (ra & 1) << 2, sa = la & 3;
        const int rb = warpN + rr;
        const int lb = rb >> 1, xb = (rb & 1) << 2, sb = lb & 3;
        #pragma unroll
        for (int ks = 0; ks < 2; ks++) {
            const int c = 2 * ks + hi;
            #pragma unroll
            for (int mt = 0; mt < 4; mt++)
                a_off[ks][mt] = (uint32_t)(la * 8 + mt * 64 + ((xa | c) ^ sa)) * 16u;
            #pragma unroll
            for (int n2 = 0; n2 < 2; n2++)
                b_off[ks][n2] = 8192u + (uint32_t)(lb * 8 + n2 * 64 + ((xb | c) ^ sb)) * 16u;
        }
    }

    float acc[4][4][4];
    #pragma unroll
    for (int mt = 0; mt < 4; mt++)
        #pragma unroll
        for (int nt = 0; nt < 4; nt++)
            #pragma unroll
            for (int c = 0; c < 4; c++) acc[mt][nt][c] = 0.f;

    const int nk = K >> 5;

    for (int s = 0; s < 3; s++) {
        const uint32_t sb_ = smem_u + s * STAGE_B;
        #pragma unroll
        for (int j = 0; j < 4; j++)
            cp_async16(sb_ + ld_dst[j], ld_src[j] + s * 32);
        cp_commit();
    }

    for (int kc = 0; kc < nk; kc++) {
        cp_wait2();
        __syncthreads();

        if (kc + 3 < nk) {
            const uint32_t sb_ = smem_u + ((kc + 3) & 3) * STAGE_B;
            #pragma unroll
            for (int j = 0; j < 4; j++)
                cp_async16(sb_ + ld_dst[j], ld_src[j] + (kc + 3) * 32);
        }
        cp_commit();

        const uint32_t st = smem_u + (kc & 3) * STAGE_B;
        #pragma unroll
        for (int ks = 0; ks < 2; ks++) {
            uint32_t bfr[4][2];
            {
                uint32_t r0, r1, r2, r3;
                LDSM4(r0, r1, r2, r3, st + b_off[ks][0]);
                bfr[0][0] = r0; bfr[1][0] = r1; bfr[0][1] = r2; bfr[1][1] = r3;
            }
            {
                uint32_t r0, r1, r2, r3;
                LDSM4(r0, r1, r2, r3, st + b_off[ks][1]);
                bfr[2][0] = r0; bfr[3][0] = r1; bfr[2][1] = r2; bfr[3][1] = r3;
            }
            #pragma unroll
            for (int mt = 0; mt < 4; mt++) {
                uint32_t af[4];
                LDSM4(af[0], af[1], af[2], af[3], st + a_off[ks][mt]);
                #pragma unroll
                for (int nt = 0; nt < 4; nt++)
                    mma_f16(acc[mt][nt], af, bfr[nt]);
            }
        }
    }

    __half* C = scratch_h(Cid);
    const __half* R = (resHid >= 0) ? scratch_h(resHid) : (const __half*)0;
    #pragma unroll
    for (int nt = 0; nt < 4; nt++) {
        const int n = n0 + warpN + nt * 8 + 2 * tig;
        const float b0 = bias[n], b1 = bias[n + 1];
        #pragma unroll
        for (int mt = 0; mt < 4; mt++) {
            const int m = m0 + warpM + mt * 16 + gid;
            float v0 = acc[mt][nt][0] + b0, v1 = acc[mt][nt][1] + b1;
            float v2 = acc[mt][nt][2] + b0, v3 = acc[mt][nt][3] + b1;
            if (relu) {
                v0 = fmaxf(v0, 0.f); v1 = fmaxf(v1, 0.f);
                v2 = fmaxf(v2, 0.f); v3 = fmaxf(v3, 0.f);
            }
            if (R) {
                const __half2 r0 = *(const __half2*)&R[(size_t)m * N + n];
                const __half2 r1 = *(const __half2*)&R[(size_t)(m + 8) * N + n];
                v0 += __half2float(r0.x); v1 += __half2float(r0.y);
                v2 += __half2float(r1.x); v3 += __half2float(r1.y);
            }
            *(uint32_t*)&C[(size_t)m * N + n]       = packh2(v0, v1);
            *(uint32_t*)&C[(size_t)(m + 8) * N + n] = packh2(v2, v3);
        }
    }
}

// ---------------------------------------------------------------------------
// FP16 flash attention (R10-validated, FROZEN)
// ---------------------------------------------------------------------------
__global__ __launch_bounds__(128)
void attn_f16()
{
    __shared__ __align__(16) uint8_t sm[16384];
    const uint32_t su = (uint32_t)__cvta_generic_to_shared(sm);

    const int nB  = blockIdx.z;
    const int h   = blockIdx.y;
    const int q0  = blockIdx.x * 128;
    const int tid = threadIdx.x;
    const int wid = tid >> 5;
    const int lane = tid & 31;
    const int gid  = lane >> 2;
    const int tig  = lane & 3;
    const int warpM = wid * 32;
    const int rr = (lane & 7) + ((lane >> 3) & 1) * 8;
    const int hi = lane >> 4;
    const float qscale = 0.125f * 1.44269504f;

    #pragma unroll
    for (int t = 0; t < 8; t++) {
        const int i = t * 128 + tid;
        const int row = i >> 3, c = i & 7;
        const __half* src = g_qkv16 + (size_t)(nB * LQ + q0 + row) * (3 * D) + h * HD + c * 8;
        *(uint4*)(sm + ATT_SEG(row, c) * 16) = *(const uint4*)src;
    }
    __syncthreads();

    uint32_t qf[2][4][4];
    #pragma unroll
    for (int mt = 0; mt < 2; mt++)
        #pragma unroll
        for (int kc = 0; kc < 4; kc++) {
            const int row = warpM + mt * 16 + rr;
            LDSM4(qf[mt][kc][0], qf[mt][kc][1], qf[mt][kc][2], qf[mt][kc][3],
                  su + ATT_SEG(row, 2 * kc + hi) * 16);
        }
    __syncthreads();

    float oac[2][8][4];
    #pragma unroll
    for (int mt = 0; mt < 2; mt++)
        #pragma unroll
        for (int nt = 0; nt < 8; nt++)
            #pragma unroll
            for (int c = 0; c < 4; c++) oac[mt][nt][c] = 0.f;
    float mrow[2][2] = {{-1e30f, -1e30f}, {-1e30f, -1e30f}};
    float lrow[2][2] = {{0.f, 0.f}, {0.f, 0.f}};

    for (int kt = 0; kt < LQ / 64; kt++) {
        #pragma unroll
        for (int t = 0; t < 4; t++) {
            const int i = t * 128 + tid;
            const int row = i >> 3, c = i & 7;
            const __half* base = g_qkv16 + (size_t)(nB * LQ + kt * 64 + row) * (3 * D) + h * HD + c * 8;
            *(uint4*)(sm + ATT_SEG(row, c) * 16)        = *(const uint4*)(base + D);
            *(uint4*)(sm + 8192 + ATT_SEG(row, c) * 16) = *(const uint4*)(base + 2 * D);
        }
        __syncthreads();

        float sacc[2][8][4];
        #pragma unroll
        for (int mt = 0; mt < 2; mt++)
            #pragma unroll
            for (int nt = 0; nt < 8; nt++)
                #pragma unroll
                for (int c = 0; c < 4; c++) sacc[mt][nt][c] = 0.f;

        #pragma unroll
        for (int ks = 0; ks < 4; ks++) {
            uint32_t bfr[8][2];
            #pragma unroll
            for (int np = 0; np < 4; np++) {
                uint32_t r0, r1, r2, r3;
                LDSM4(r0, r1, r2, r3, su + ATT_SEG(np * 16 + rr, 2 * ks + hi) * 16);
                bfr[2 * np][0] = r0; bfr[2 * np + 1][0] = r1;
                bfr[2 * np][1] = r2; bfr[2 * np + 1][1] = r3;
            }
            #pragma unroll
            for (int mt = 0; mt < 2; mt++)
                #pragma unroll
                for (int nt = 0; nt < 8; nt++)
                    mma_f16(sacc[mt][nt], qf[mt][ks], bfr[nt]);
        }

        #pragma unroll
        for (int mt = 0; mt < 2; mt++) {
            #pragma unroll
            for (int nt = 0; nt < 8; nt++) {
                sacc[mt][nt][0] *= qscale; sacc[mt][nt][1] *= qscale;
                sacc[mt][nt][2] *= qscale; sacc[mt][nt][3] *= qscale;
            }
            float mx0 = -1e30f, mx1 = -1e30f;
            #pragma unroll
            for (int nt = 0; nt < 8; nt++) {
                mx0 = fmaxf(mx0, fmaxf(sacc[mt][nt][0], sacc[mt][nt][1]));
                mx1 = fmaxf(mx1, fmaxf(sacc[mt][nt][2], sacc[mt][nt][3]));
            }
            mx0 = fmaxf(mx0, __shfl_xor_sync(0xFFFFFFFFu, mx0, 1));
            mx0 = fmaxf(mx0, __shfl_xor_sync(0xFFFFFFFFu, mx0, 2));
            mx1 = fmaxf(mx1, __shfl_xor_sync(0xFFFFFFFFu, mx1, 1));
            mx1 = fmaxf(mx1, __shfl_xor_sync(0xFFFFFFFFu, mx1, 2));

            const float mn0 = fmaxf(mrow[mt][0], mx0);
            const float mn1 = fmaxf(mrow[mt][1], mx1);
            const float cr0 = exp2f(mrow[mt][0] - mn0);
            const float cr1 = exp2f(mrow[mt][1] - mn1);
            mrow[mt][0] = mn0;
            mrow[mt][1] = mn1;

            float ls0 = 0.f, ls1 = 0.f;
            #pragma unroll
            for (int nt = 0; nt < 8; nt++) {
                sacc[mt][nt][0] = exp2f(sacc[mt][nt][0] - mn0);
                sacc[mt][nt][1] = exp2f(sacc[mt][nt][1] - mn0);
                sacc[mt][nt][2] = exp2f(sacc[mt][nt][2] - mn1);
                sacc[mt][nt][3] = exp2f(sacc[mt][nt][3] - mn1);
                ls0 += sacc[mt][nt][0] + sacc[mt][nt][1];
                ls1 += sacc[mt][nt][2] + sacc[mt][nt][3];
            }
            ls0 += __shfl_xor_sync(0xFFFFFFFFu, ls0, 1);
            ls0 += __shfl_xor_sync(0xFFFFFFFFu, ls0, 2);
            ls1 += __shfl_xor_sync(0xFFFFFFFFu, ls1, 1);
            ls1 += __shfl_xor_sync(0xFFFFFFFFu, ls1, 2);
            lrow[mt][0] = lrow[mt][0] * cr0 + ls0;
            lrow[mt][1] = lrow[mt][1] * cr1 + ls1;

            #pragma unroll
            for (int nt = 0; nt < 8; nt++) {
                oac[mt][nt][0] *= cr0; oac[mt][nt][1] *= cr0;
                oac[mt][nt][2] *= cr1; oac[mt][nt][3] *= cr1;
            }
        }

        #pragma unroll
        for (int kc = 0; kc < 4; kc++) {
            uint32_t vb[8][2];
            #pragma unroll
            for (int dp = 0; dp < 4; dp++) {
                uint32_t r0, r1, r2, r3;
                LDSM4T(r0, r1, r2, r3, su + 8192 + ATT_SEG(kc * 16 + rr, 2 * dp + hi) * 16);
                vb[2 * dp][0] = r0; vb[2 * dp][1] = r1;
                vb[2 * dp + 1][0] = r2; vb[2 * dp + 1][1] = r3;
            }
            uint32_t pa[2][4];
            #pragma unroll
            for (int mt = 0; mt < 2; mt++) {
                pa[mt][0] = packh2(sacc[mt][2 * kc][0],     sacc[mt][2 * kc][1]);
                pa[mt][1] = packh2(sacc[mt][2 * kc][2],     sacc[mt][2 * kc][3]);
                pa[mt][2] = packh2(sacc[mt][2 * kc + 1][0], sacc[mt][2 * kc + 1][1]);
                pa[mt][3] = packh2(sacc[mt][2 * kc + 1][2], sacc[mt][2 * kc + 1][3]);
            }
            #pragma unroll
            for (int mt = 0; mt < 2; mt++)
                #pragma unroll
                for (int ntd = 0; ntd < 8; ntd++)
                    mma_f16(oac[mt][ntd], pa[mt], vb[ntd]);
        }
        __syncthreads();
    }

    #pragma unroll
    for (int mt = 0; mt < 2; mt++) {
        const float inv0 = 1.f / lrow[mt][0];
        const float inv1 = 1.f / lrow[mt][1];
        const int grow = nB * LQ + q0 + warpM + mt * 16 + gid;
        #pragma unroll
        for (int ntd = 0; ntd < 8; ntd++) {
            const int col = h * HD + ntd * 8 + 2 * tig;
            *(uint32_t*)&g_attn16[(size_t)grow * D + col] =
                packh2(oac[mt][ntd][0] * inv0, oac[mt][ntd][1] * inv0);
            *(uint32_t*)&g_attn16[(size_t)(grow + 8) * D + col] =
                packh2(oac[mt][ntd][2] * inv1, oac[mt][ntd][3] * inv1);
        }
    }
}

// ---------------------------------------------------------------------------
// Pure LayerNorm over a pre-summed fp16 input.
// out: fp32 external (outF32) or fp16 scratch (outHid).
// ---------------------------------------------------------------------------
__global__ __launch_bounds__(256)
void ln_kernel(int aHid, const float* __restrict__ gamma,
               const float* __restrict__ beta,
               float* __restrict__ outF32, int outHid)
{
    const __half* a = scratch_h(aHid);
    const int row = blockIdx.x;
    const int tid = threadIdx.x;
    const size_t base = (size_t)row * D;

    float v[4];
    float s = 0.f, s2 = 0.f;
    #pragma unroll
    for (int i = 0; i < 4; i++) {
        int col = tid + i * 256;
        float x = __half2float(a[base + col]);
        v[i] = x;
        s  += x;
        s2 += x * x;
    }
    #pragma unroll
    for (int off = 16; off; off >>= 1) {
        s  += __shfl_xor_sync(0xFFFFFFFFu, s,  off);
        s2 += __shfl_xor_sync(0xFFFFFFFFu, s2, off);
    }
    __shared__ float rs[8], rs2[8];
    const int warp = tid >> 5, lane = tid & 31;
    if (lane == 0) { rs[warp] = s; rs2[warp] = s2; }
    __syncthreads();
    float ts = 0.f, ts2 = 0.f;
    #pragma unroll
    for (int w = 0; w < 8; w++) { ts += rs[w]; ts2 += rs2[w]; }

    const float mu  = ts * (1.f / D);
    const float var = ts2 * (1.f / D) - mu * mu;
    const float inv = rsqrtf(var + EPS);

    __half* ho = (outHid >= 0) ? scratch_h(outHid) : (__half*)0;
    #pragma unroll
    for (int i = 0; i < 4; i++) {
        int col = tid + i * 256;
        float r = (v[i] - mu) * inv * gamma[col] + beta[col];
        if (outF32) outF32[base + col] = r;
        if (ho)     ho[base + col] = __float2half(r);
    }
}

// ---------------------------------------------------------------------------
// Launch
// ---------------------------------------------------------------------------
extern "C" void kernel_launch(void* const* d_in, const int* in_sizes, int n_in,
                              void* d_out, int out_size)
{
    const float* x     = (const float*)d_in[0];
    const float* w_qkv = (const float*)d_in[1];
    const float* b_qkv = (const float*)d_in[2];
    const float* w_o   = (const float*)d_in[3];
    const float* b_o   = (const float*)d_in[4];
    const float* g1    = (const float*)d_in[5];
    const float* be1   = (const float*)d_in[6];
    const float* w1    = (const float*)d_in[7];
    const float* b1    = (const float*)d_in[8];
    const float* w2    = (const float*)d_in[9];
    const float* b2    = (const float*)d_in[10];
    const float* g2    = (const float*)d_in[11];
    const float* be2   = (const float*)d_in[12];
    float* out = (float*)d_out;

    cudaFuncSetAttribute(gemm_f16,
                         cudaFuncAttributeMaxDynamicSharedMemorySize, GEMM_SMEM);

    // 0. fused operand prep (cvt x + 4 transposes)
    prep_k<<<16384, 256>>>(x, w_qkv, w_o, w1, w2);

    // 1. QKV: x16 (h0) @ wqkvT16 -> g_qkv16 (fp16)
    gemm_f16<<<dim3(3 * D / 128, MROWS / 128), 256, GEMM_SMEM>>>(
        0, 4, b_qkv, 8, -1, MROWS, 3 * D, D, 0);

    // 2. attention -> g_attn16 (h1)
    attn_f16<<<dim3(LQ / 128, H_, NB), 128>>>();

    // 3. proj + residual x16: attn16 @ woT16 + x16 -> hpre16 (h0, in place)
    gemm_f16<<<dim3(D / 128, MROWS / 128), 256, GEMM_SMEM>>>(
        1, 5, b_o, 0, 0, MROWS, D, D, 0);

    // 4. h = LN(hpre16) -> h16 (h2)
    ln_kernel<<<MROWS, 256>>>(0, g1, be1, nullptr, 2);

    // 5. FF1: h16 @ w1T16 + ReLU -> g_ff116 (h3)
    gemm_f16<<<dim3(FF / 128, MROWS / 128), 256, GEMM_SMEM>>>(
        2, 6, b1, 3, -1, MROWS, FF, D, 1);

    // 6. FF2 + residual h16: ff116 @ w2T16 + h16 -> sum16 (h1)
    gemm_f16<<<dim3(D / 128, MROWS / 128), 256, GEMM_SMEM>>>(
        3, 7, b2, 1, 2, MROWS, D, FF, 0);

    // 7. out = LN(sum16) -> fp32 output
    ln_kernel<<<MROWS, 256>>>(1, g2, be2, out, -1);
}

// round 17
// speedup vs baseline: 1.0535x; 1.0535x over previous
#include <cuda_runtime.h>
#include <cuda_fp16.h>
#include <math.h>
#include <stdint.h>

// Problem constants
#define D     1024
#define H_    16
#define HD    64
#define FF    4096
#define NB    2
#define LQ    2048
#define MROWS (NB * LQ)   // 4096
#define EPS   1e-5f

// ---------------------------------------------------------------------------
// Scratch (device globals — no allocation allowed)
// ---------------------------------------------------------------------------
__device__ __half g_x16   [MROWS * D];    // h id 0  (x16, later proj16)
__device__ __half g_attn16[MROWS * D];    // h id 1  (attn16, later ff216)
__device__ __half g_h16   [MROWS * D];    // h id 2
__device__ __half g_ff116 [MROWS * FF];   // h id 3
__device__ __half g_wqkvT16[3 * D * D];   // h id 4
__device__ __half g_woT16 [D * D];        // h id 5
__device__ __half g_w1T16 [FF * D];       // h id 6
__device__ __half g_w2T16 [D * FF];       // h id 7
__device__ __half g_qkv16 [MROWS * 3 * D];// h id 8

__device__ __forceinline__ __half* scratch_h(int id) {
    switch (id) {
        case 0:  return g_x16;
        case 1:  return g_attn16;
        case 2:  return g_h16;
        case 3:  return g_ff116;
        case 4:  return g_wqkvT16;
        case 5:  return g_woT16;
        case 6:  return g_w1T16;
        case 7:  return g_w2T16;
        default: return g_qkv16;
    }
}

// ---------------------------------------------------------------------------
// mma / async helpers (base sm_103 target OK)
// ---------------------------------------------------------------------------
__device__ __forceinline__ void mma_f16(float* c, const uint32_t* a, const uint32_t* b) {
    asm volatile(
        "mma.sync.aligned.m16n8k16.row.col.f32.f16.f16.f32 "
        "{%0,%1,%2,%3}, {%4,%5,%6,%7}, {%8,%9}, {%0,%1,%2,%3};"
        : "+f"(c[0]), "+f"(c[1]), "+f"(c[2]), "+f"(c[3])
        : "r"(a[0]), "r"(a[1]), "r"(a[2]), "r"(a[3]),
          "r"(b[0]), "r"(b[1]));
}

__device__ __forceinline__ uint32_t packh2(float a, float b) {
    __half2 h = __floats2half2_rn(a, b);
    return *(uint32_t*)&h;
}

__device__ __forceinline__ void cp_async16(uint32_t dst, const void* src) {
    asm volatile("cp.async.cg.shared.global [%0], [%1], 16;" :: "r"(dst), "l"(src));
}
__device__ __forceinline__ void cp_commit() {
    asm volatile("cp.async.commit_group;" ::: "memory");
}
__device__ __forceinline__ void cp_wait2() {
    asm volatile("cp.async.wait_group 2;" ::: "memory");
}
__device__ __forceinline__ void cp_wait1() {
    asm volatile("cp.async.wait_group 1;" ::: "memory");
}
__device__ __forceinline__ void cp_wait0() {
    asm volatile("cp.async.wait_group 0;" ::: "memory");
}

#define LDSM4(r0, r1, r2, r3, addr) \
    asm volatile("ldmatrix.sync.aligned.m8n8.x4.shared.b16 {%0,%1,%2,%3}, [%4];" \
                 : "=r"(r0), "=r"(r1), "=r"(r2), "=r"(r3) : "r"(addr))

#define LDSM4T(r0, r1, r2, r3, addr) \
    asm volatile("ldmatrix.sync.aligned.m8n8.x4.trans.shared.b16 {%0,%1,%2,%3}, [%4];" \
                 : "=r"(r0), "=r"(r1), "=r"(r2), "=r"(r3) : "r"(addr))

// 64B-row XOR swizzle (GEMM stages)
__device__ __forceinline__ int phys16(int row, int c) {
    return (row >> 1) * 8 + ((((row & 1) << 2) | c) ^ ((row >> 1) & 3));
}
// 128B-row XOR swizzle (attention tiles)
#define ATT_SEG(row, c) (((row) * 8) + ((c) ^ ((row) & 7)))

// ---------------------------------------------------------------------------
// Fused operand prep (R14-validated)
// ---------------------------------------------------------------------------
__device__ __forceinline__ void transpose_tile(const float* __restrict__ src,
                                               __half* __restrict__ dst,
                                               int R, int C, int bx, int by,
                                               float (*t)[33])
{
    const int tx = threadIdx.x & 31;
    const int ty = threadIdx.x >> 5;
    #pragma unroll
    for (int i = 0; i < 32; i += 8)
        t[ty + i][tx] = src[(size_t)(by + ty + i) * C + bx + tx];
    __syncthreads();
    #pragma unroll
    for (int i = 0; i < 32; i += 8)
        dst[(size_t)(bx + ty + i) * R + by + tx] = __float2half(t[tx][ty + i]);
}

__global__ __launch_bounds__(256)
void prep_k(const float* __restrict__ x,
            const float* __restrict__ w_qkv,
            const float* __restrict__ w_o,
            const float* __restrict__ w1,
            const float* __restrict__ w2)
{
    __shared__ float t[32][33];
    const int id = blockIdx.x;

    if (id < 4096) {
        uint32_t* d = (uint32_t*)g_x16;
        const int i = id * 256 + threadIdx.x;
        const float4 v = ((const float4*)x)[i];
        d[i * 2 + 0] = packh2(v.x, v.y);
        d[i * 2 + 1] = packh2(v.z, v.w);
    } else if (id < 7168) {
        const int b = id - 4096;
        transpose_tile(w_qkv, g_wqkvT16, D, 3 * D, (b % 96) * 32, (b / 96) * 32, t);
    } else if (id < 8192) {
        const int b = id - 7168;
        transpose_tile(w_o, g_woT16, D, D, (b % 32) * 32, (b / 32) * 32, t);
    } else if (id < 12288) {
        const int b = id - 8192;
        transpose_tile(w1, g_w1T16, D, FF, (b % 128) * 32, (b / 128) * 32, t);
    } else {
        const int b = id - 12288;
        transpose_tile(w2, g_w2T16, FF, D, (b % 32) * 32, (b / 32) * 32, t);
    }
}

// ---------------------------------------------------------------------------
// FP16 GEMM 128x128 (R10-validated, FROZEN)
// ---------------------------------------------------------------------------
#define STAGE_B 16384
#define GEMM_SMEM (4 * STAGE_B)   // 65536

__global__ __launch_bounds__(256)
void gemm_f16(int Aid, int Bid, const float* __restrict__ bias,
              int Cid, int M, int N, int K, int relu)
{
    extern __shared__ char smem[];
    const uint32_t smem_u = (uint32_t)__cvta_generic_to_shared(smem);

    const __half* A  = scratch_h(Aid);
    const __half* Bt = scratch_h(Bid);

    const int tid  = threadIdx.x;
    const int wid  = tid >> 5;
    const int lane = tid & 31;
    const int gid  = lane >> 2;
    const int tig  = lane & 3;
    const int warpM = (wid & 1) * 64;
    const int warpN = (wid >> 1) * 32;
    const int m0 = blockIdx.y * 128;
    const int n0 = blockIdx.x * 128;

    uint32_t ld_dst[4];
    const __half* ld_src[4];
    #pragma unroll
    for (int j = 0; j < 4; j++) {
        const int s   = j * 256 + tid;
        const int isB = s >= 512;
        const int ss  = s & 511;
        const int row = ss >> 2;
        const int c   = ss & 3;
        ld_dst[j] = (isB ? 8192u : 0u) + (uint32_t)phys16(row, c) * 16u;
        ld_src[j] = (isB ? Bt + (size_t)(n0 + row) * K
                         : A  + (size_t)(m0 + row) * K) + c * 8;
    }

    const int hi = lane >> 4;
    const int rr = (lane & 7) + ((lane >> 3) & 1) * 8;
    uint32_t a_off[2][4], b_off[2][2];
    {
        const int ra = warpM + rr;
        const int la = ra >> 1, xa = (ra & 1) << 2, sa = la & 3;
        const int rb = warpN + rr;
        const int lb = rb >> 1, xb = (rb & 1) << 2, sb = lb & 3;
        #pragma unroll
        for (int ks = 0; ks < 2; ks++) {
            const int c = 2 * ks + hi;
            #pragma unroll
            for (int mt = 0; mt < 4; mt++)
                a_off[ks][mt] = (uint32_t)(la * 8 + mt * 64 + ((xa | c) ^ sa)) * 16u;
            #pragma unroll
            for (int n2 = 0; n2 < 2; n2++)
                b_off[ks][n2] = 8192u + (uint32_t)(lb * 8 + n2 * 64 + ((xb | c) ^ sb)) * 16u;
        }
    }

    float acc[4][4][4];
    #pragma unroll
    for (int mt = 0; mt < 4; mt++)
        #pragma unroll
        for (int nt = 0; nt < 4; nt++)
            #pragma unroll
            for (int c = 0; c < 4; c++) acc[mt][nt][c] = 0.f;

    const int nk = K >> 5;

    for (int s = 0; s < 3; s++) {
        const uint32_t sb_ = smem_u + s * STAGE_B;
        #pragma unroll
        for (int j = 0; j < 4; j++)
            cp_async16(sb_ + ld_dst[j], ld_src[j] + s * 32);
        cp_commit();
    }

    for (int kc = 0; kc < nk; kc++) {
        cp_wait2();
        __syncthreads();

        if (kc + 3 < nk) {
            const uint32_t sb_ = smem_u + ((kc + 3) & 3) * STAGE_B;
            #pragma unroll
            for (int j = 0; j < 4; j++)
                cp_async16(sb_ + ld_dst[j], ld_src[j] + (kc + 3) * 32);
        }
        cp_commit();

        const uint32_t st = smem_u + (kc & 3) * STAGE_B;
        #pragma unroll
        for (int ks = 0; ks < 2; ks++) {
            uint32_t bfr[4][2];
            {
                uint32_t r0, r1, r2, r3;
                LDSM4(r0, r1, r2, r3, st + b_off[ks][0]);
                bfr[0][0] = r0; bfr[1][0] = r1; bfr[0][1] = r2; bfr[1][1] = r3;
            }
            {
                uint32_t r0, r1, r2, r3;
                LDSM4(r0, r1, r2, r3, st + b_off[ks][1]);
                bfr[2][0] = r0; bfr[3][0] = r1; bfr[2][1] = r2; bfr[3][1] = r3;
            }
            #pragma unroll
            for (int mt = 0; mt < 4; mt++) {
                uint32_t af[4];
                LDSM4(af[0], af[1], af[2], af[3], st + a_off[ks][mt]);
                #pragma unroll
                for (int nt = 0; nt < 4; nt++)
                    mma_f16(acc[mt][nt], af, bfr[nt]);
            }
        }
    }

    __half* C = scratch_h(Cid);
    #pragma unroll
    for (int nt = 0; nt < 4; nt++) {
        const int n = n0 + warpN + nt * 8 + 2 * tig;
        const float b0 = bias[n], b1 = bias[n + 1];
        #pragma unroll
        for (int mt = 0; mt < 4; mt++) {
            const int m = m0 + warpM + mt * 16 + gid;
            float v0 = acc[mt][nt][0] + b0, v1 = acc[mt][nt][1] + b1;
            float v2 = acc[mt][nt][2] + b0, v3 = acc[mt][nt][3] + b1;
            if (relu) {
                v0 = fmaxf(v0, 0.f); v1 = fmaxf(v1, 0.f);
                v2 = fmaxf(v2, 0.f); v3 = fmaxf(v3, 0.f);
            }
            *(uint32_t*)&C[(size_t)m * N + n]       = packh2(v0, v1);
            *(uint32_t*)&C[(size_t)(m + 8) * N + n] = packh2(v2, v3);
        }
    }
}

// ---------------------------------------------------------------------------
// FP16 flash attention, cp.async double-buffered K/V (2 x 16KB stages).
// Compute/softmax sections identical to R10/R15.
// ---------------------------------------------------------------------------
#define NT_ATT (LQ / 64)   // 32

__global__ __launch_bounds__(128)
void attn_f16()
{
    __shared__ __align__(16) uint8_t sm[2 * 16384];
    const uint32_t su = (uint32_t)__cvta_generic_to_shared(sm);

    const int nB  = blockIdx.z;
    const int h   = blockIdx.y;
    const int q0  = blockIdx.x * 128;
    const int tid = threadIdx.x;
    const int wid = tid >> 5;
    const int lane = tid & 31;
    const int gid  = lane >> 2;
    const int tig  = lane & 3;
    const int warpM = wid * 32;
    const int rr = (lane & 7) + ((lane >> 3) & 1) * 8;
    const int hi = lane >> 4;
    const float qscale = 0.125f * 1.44269504f;

    // ---- stage Q (uses stage-0 area), extract frags ----
    #pragma unroll
    for (int t = 0; t < 8; t++) {
        const int i = t * 128 + tid;
        const int row = i >> 3, c = i & 7;
        const __half* src = g_qkv16 + (size_t)(nB * LQ + q0 + row) * (3 * D) + h * HD + c * 8;
        *(uint4*)(sm + ATT_SEG(row, c) * 16) = *(const uint4*)src;
    }
    __syncthreads();

    uint32_t qf[2][4][4];
    #pragma unroll
    for (int mt = 0; mt < 2; mt++)
        #pragma unroll
        for (int kc = 0; kc < 4; kc++) {
            const int row = warpM + mt * 16 + rr;
            LDSM4(qf[mt][kc][0], qf[mt][kc][1], qf[mt][kc][2], qf[mt][kc][3],
                  su + ATT_SEG(row, 2 * kc + hi) * 16);
        }
    __syncthreads();

    // ---- K/V loader precompute (4 (row,c) slots per thread) ----
    uint32_t kv_dst[4];                 // seg offset within a stage (K side)
    const __half* kv_src[4];            // K source for tile 0; V = +D
    #pragma unroll
    for (int t = 0; t < 4; t++) {
        const int i = t * 128 + tid;
        const int row = i >> 3, c = i & 7;
        kv_dst[t] = (uint32_t)ATT_SEG(row, c) * 16u;
        kv_src[t] = g_qkv16 + (size_t)(nB * LQ + row) * (3 * D) + h * HD + c * 8 + D;
    }
    const size_t tile_step = (size_t)64 * 3 * D;   // elements per key-tile

    // prologue: tile 0 -> stage 0
    #pragma unroll
    for (int t = 0; t < 4; t++) {
        cp_async16(su +        kv_dst[t], kv_src[t]);
        cp_async16(su + 8192 + kv_dst[t], kv_src[t] + D);
    }
    cp_commit();

    float oac[2][8][4];
    #pragma unroll
    for (int mt = 0; mt < 2; mt++)
        #pragma unroll
        for (int nt = 0; nt < 8; nt++)
            #pragma unroll
            for (int c = 0; c < 4; c++) oac[mt][nt][c] = 0.f;
    float mrow[2][2] = {{-1e30f, -1e30f}, {-1e30f, -1e30f}};
    float lrow[2][2] = {{0.f, 0.f}, {0.f, 0.f}};

    for (int kt = 0; kt < NT_ATT; kt++) {
        __syncthreads();   // all warps done computing tile kt-1 (its stage gets overwritten next)

        if (kt + 1 < NT_ATT) {
            const uint32_t sb_ = su + ((kt + 1) & 1) * 16384;
            const size_t off = (size_t)(kt + 1) * tile_step;
            #pragma unroll
            for (int t = 0; t < 4; t++) {
                cp_async16(sb_ +        kv_dst[t], kv_src[t] + off);
                cp_async16(sb_ + 8192 + kv_dst[t], kv_src[t] + off + D);
            }
            cp_commit();
            cp_wait1();    // tile kt complete, kt+1 in flight
        } else {
            cp_wait0();    // last tile
        }
        __syncthreads();

        const uint32_t stg = su + (kt & 1) * 16384;

        float sacc[2][8][4];
        #pragma unroll
        for (int mt = 0; mt < 2; mt++)
            #pragma unroll
            for (int nt = 0; nt < 8; nt++)
                #pragma unroll
                for (int c = 0; c < 4; c++) sacc[mt][nt][c] = 0.f;

        #pragma unroll
        for (int ks = 0; ks < 4; ks++) {
            uint32_t bfr[8][2];
            #pragma unroll
            for (int np = 0; np < 4; np++) {
                uint32_t r0, r1, r2, r3;
                LDSM4(r0, r1, r2, r3, stg + ATT_SEG(np * 16 + rr, 2 * ks + hi) * 16);
                bfr[2 * np][0] = r0; bfr[2 * np + 1][0] = r1;
                bfr[2 * np][1] = r2; bfr[2 * np + 1][1] = r3;
            }
            #pragma unroll
            for (int mt = 0; mt < 2; mt++)
                #pragma unroll
                for (int nt = 0; nt < 8; nt++)
                    mma_f16(sacc[mt][nt], qf[mt][ks], bfr[nt]);
        }

        #pragma unroll
        for (int mt = 0; mt < 2; mt++) {
            #pragma unroll
            for (int nt = 0; nt < 8; nt++) {
                sacc[mt][nt][0] *= qscale; sacc[mt][nt][1] *= qscale;
                sacc[mt][nt][2] *= qscale; sacc[mt][nt][3] *= qscale;
            }
            float mx0 = -1e30f, mx1 = -1e30f;
            #pragma unroll
            for (int nt = 0; nt < 8; nt++) {
                mx0 = fmaxf(mx0, fmaxf(sacc[mt][nt][0], sacc[mt][nt][1]));
                mx1 = fmaxf(mx1, fmaxf(sacc[mt][nt][2], sacc[mt][nt][3]));
            }
            mx0 = fmaxf(mx0, __shfl_xor_sync(0xFFFFFFFFu, mx0, 1));
            mx0 = fmaxf(mx0, __shfl_xor_sync(0xFFFFFFFFu, mx0, 2));
            mx1 = fmaxf(mx1, __shfl_xor_sync(0xFFFFFFFFu, mx1, 1));
            mx1 = fmaxf(mx1, __shfl_xor_sync(0xFFFFFFFFu, mx1, 2));

            const float mn0 = fmaxf(mrow[mt][0], mx0);
            const float mn1 = fmaxf(mrow[mt][1], mx1);
            const float cr0 = exp2f(mrow[mt][0] - mn0);
            const float cr1 = exp2f(mrow[mt][1] - mn1);
            mrow[mt][0] = mn0;
            mrow[mt][1] = mn1;

            float ls0 = 0.f, ls1 = 0.f;
            #pragma unroll
            for (int nt = 0; nt < 8; nt++) {
                sacc[mt][nt][0] = exp2f(sacc[mt][nt][0] - mn0);
                sacc[mt][nt][1] = exp2f(sacc[mt][nt][1] - mn0);
                sacc[mt][nt][2] = exp2f(sacc[mt][nt][2] - mn1);
                sacc[mt][nt][3] = exp2f(sacc[mt][nt][3] - mn1);
                ls0 += sacc[mt][nt][0] + sacc[mt][nt][1];
                ls1 += sacc[mt][nt][2] + sacc[mt][nt][3];
            }
            ls0 += __shfl_xor_sync(0xFFFFFFFFu, ls0, 1);
            ls0 += __shfl_xor_sync(0xFFFFFFFFu, ls0, 2);
            ls1 += __shfl_xor_sync(0xFFFFFFFFu, ls1, 1);
            ls1 += __shfl_xor_sync(0xFFFFFFFFu, ls1, 2);
            lrow[mt][0] = lrow[mt][0] * cr0 + ls0;
            lrow[mt][1] = lrow[mt][1] * cr1 + ls1;

            #pragma unroll
            for (int nt = 0; nt < 8; nt++) {
                oac[mt][nt][0] *= cr0; oac[mt][nt][1] *= cr0;
                oac[mt][nt][2] *= cr1; oac[mt][nt][3] *= cr1;
            }
        }

        #pragma unroll
        for (int kc = 0; kc < 4; kc++) {
            uint32_t vb[8][2];
            #pragma unroll
            for (int dp = 0; dp < 4; dp++) {
                uint32_t r0, r1, r2, r3;
                LDSM4T(r0, r1, r2, r3, stg + 8192 + ATT_SEG(kc * 16 + rr, 2 * dp + hi) * 16);
                vb[2 * dp][0] = r0; vb[2 * dp][1] = r1;
                vb[2 * dp + 1][0] = r2; vb[2 * dp + 1][1] = r3;
            }
            uint32_t pa[2][4];
            #pragma unroll
            for (int mt = 0; mt < 2; mt++) {
                pa[mt][0] = packh2(sacc[mt][2 * kc][0],     sacc[mt][2 * kc][1]);
                pa[mt][1] = packh2(sacc[mt][2 * kc][2],     sacc[mt][2 * kc][3]);
                pa[mt][2] = packh2(sacc[mt][2 * kc + 1][0], sacc[mt][2 * kc + 1][1]);
                pa[mt][3] = packh2(sacc[mt][2 * kc + 1][2], sacc[mt][2 * kc + 1][3]);
            }
            #pragma unroll
            for (int mt = 0; mt < 2; mt++)
                #pragma unroll
                for (int ntd = 0; ntd < 8; ntd++)
                    mma_f16(oac[mt][ntd], pa[mt], vb[ntd]);
        }
    }

    #pragma unroll
    for (int mt = 0; mt < 2; mt++) {
        const float inv0 = 1.f / lrow[mt][0];
        const float inv1 = 1.f / lrow[mt][1];
        const int grow = nB * LQ + q0 + warpM + mt * 16 + gid;
        #pragma unroll
        for (int ntd = 0; ntd < 8; ntd++) {
            const int col = h * HD + ntd * 8 + 2 * tig;
            *(uint32_t*)&g_attn16[(size_t)grow * D + col] =
                packh2(oac[mt][ntd][0] * inv0, oac[mt][ntd][1] * inv0);
            *(uint32_t*)&g_attn16[(size_t)(grow + 8) * D + col] =
                packh2(oac[mt][ntd][2] * inv1, oac[mt][ntd][3] * inv1);
        }
    }
}

// ---------------------------------------------------------------------------
// Residual add + LayerNorm, mixed dtype in/out (R15-validated)
// ---------------------------------------------------------------------------
__global__ __launch_bounds__(256)
void add_ln_kernel(int aHid, int bHid, const float* __restrict__ bF32,
                   const float* __restrict__ gamma,
                   const float* __restrict__ beta,
                   float* __restrict__ outF32, int outHid)
{
    const __half* a = scratch_h(aHid);
    const __half* bh = (bHid >= 0) ? scratch_h(bHid) : (const __half*)0;

    const int row = blockIdx.x;
    const int tid = threadIdx.x;
    const size_t base = (size_t)row * D;

    float v[4];
    float s = 0.f, s2 = 0.f;
    #pragma unroll
    for (int i = 0; i < 4; i++) {
        int col = tid + i * 256;
        float av = __half2float(a[base + col]);
        float bv = bh ? __half2float(bh[base + col]) : bF32[base + col];
        float x = av + bv;
        v[i] = x;
        s  += x;
        s2 += x * x;
    }
    #pragma unroll
    for (int off = 16; off; off >>= 1) {
        s  += __shfl_xor_sync(0xFFFFFFFFu, s,  off);
        s2 += __shfl_xor_sync(0xFFFFFFFFu, s2, off);
    }
    __shared__ float rs[8], rs2[8];
    const int warp = tid >> 5, lane = tid & 31;
    if (lane == 0) { rs[warp] = s; rs2[warp] = s2; }
    __syncthreads();
    float ts = 0.f, ts2 = 0.f;
    #pragma unroll
    for (int w = 0; w < 8; w++) { ts += rs[w]; ts2 += rs2[w]; }

    const float mu  = ts * (1.f / D);
    const float var = ts2 * (1.f / D) - mu * mu;
    const float inv = rsqrtf(var + EPS);

    __half* ho = (outHid >= 0) ? scratch_h(outHid) : (__half*)0;
    #pragma unroll
    for (int i = 0; i < 4; i++) {
        int col = tid + i * 256;
        float r = (v[i] - mu) * inv * gamma[col] + beta[col];
        if (outF32) outF32[base + col] = r;
        if (ho)     ho[base + col] = __float2half(r);
    }
}

// ---------------------------------------------------------------------------
// Launch (R15 dataflow)
// ---------------------------------------------------------------------------
extern "C" void kernel_launch(void* const* d_in, const int* in_sizes, int n_in,
                              void* d_out, int out_size)
{
    const float* x     = (const float*)d_in[0];
    const float* w_qkv = (const float*)d_in[1];
    const float* b_qkv = (const float*)d_in[2];
    const float* w_o   = (const float*)d_in[3];
    const float* b_o   = (const float*)d_in[4];
    const float* g1    = (const float*)d_in[5];
    const float* be1   = (const float*)d_in[6];
    const float* w1    = (const float*)d_in[7];
    const float* b1    = (const float*)d_in[8];
    const float* w2    = (const float*)d_in[9];
    const float* b2    = (const float*)d_in[10];
    const float* g2    = (const float*)d_in[11];
    const float* be2   = (const float*)d_in[12];
    float* out = (float*)d_out;

    cudaFuncSetAttribute(gemm_f16,
                         cudaFuncAttributeMaxDynamicSharedMemorySize, GEMM_SMEM);

    // 0. fused operand prep (cvt x + 4 transposes)
    prep_k<<<16384, 256>>>(x, w_qkv, w_o, w1, w2);

    // 1. QKV: x16 (h0) @ wqkvT16 -> g_qkv16 (fp16)
    gemm_f16<<<dim3(3 * D / 128, MROWS / 128), 256, GEMM_SMEM>>>(
        0, 4, b_qkv, 8, MROWS, 3 * D, D, 0);

    // 2. attention -> g_attn16 (h1)
    attn_f16<<<dim3(LQ / 128, H_, NB), 128>>>();

    // 3. proj: attn16 (h1) @ woT16 -> proj16 (h0, reusing g_x16)
    gemm_f16<<<dim3(D / 128, MROWS / 128), 256, GEMM_SMEM>>>(
        1, 5, b_o, 0, MROWS, D, D, 0);

    // 4. h = LN(proj16 + x) -> h16 (h2)
    add_ln_kernel<<<MROWS, 256>>>(0, -1, x, g1, be1, nullptr, 2);

    // 5. FF1: h16 @ w1T16 + ReLU -> g_ff116 (h3)
    gemm_f16<<<dim3(FF / 128, MROWS / 128), 256, GEMM_SMEM>>>(
        2, 6, b1, 3, MROWS, FF, D, 1);

    // 6. FF2: ff116 (h3) @ w2T16 -> ff216 (h1, reusing g_attn16)
    gemm_f16<<<dim3(D / 128, MROWS / 128), 256, GEMM_SMEM>>>(
        3, 7, b2, 1, MROWS, D, FF, 0);

    // 7. out = LN(h16 + ff216) -> fp32 output
    add_ln_kernel<<<MROWS, 256>>>(2, 1, nullptr, g2, be2, out, -1);
}